// round 14
// baseline (speedup 1.0000x reference)
#include <cuda_runtime.h>
#include <stdint.h>

#define MAXN 10000
#define MAXE 640000
#define C 128
#define STEPS 3

// ---------------- scratch (no allocations allowed) ----------------
__device__ int   g_is64;
__device__ int   g_deg[MAXN];
__device__ int   g_row_ptr[MAXN + 1];
__device__ int   g_col[MAXE];       // holds src*32 (float4-unit row offsets)
__device__ int2  g_dr[MAXE];        // packed (dst, rank) per edge
__device__ float g_inv_deg[MAXN];
__device__ float g_h[2][MAXN * C];  // h1, h2 (h0 = input x; h3 fused into gate)

// Zero the degree array; thread 0 also detects whether edge_index is int64
// or int32. CRITICAL: only sample int64 elements in [0, E/2), which is
// in-bounds under BOTH interpretations (an int32 buffer of 2E ints spans
// exactly E int64 elements; an int64 buffer spans 2E). If the data is
// really int32, an int64 read packs two node indices; the high word is a
// random index that is nonzero w.p. ~0.9999, making the value >= 2^32 >> N
// -> flags int32. 64 strided samples make wrong detection ~impossible.
__global__ void k_init(const void* ei, int E, int N) {
    int i = blockIdx.x * blockDim.x + threadIdx.x;
    if (i < N) g_deg[i] = 0;
    if (i == 0) {
        const long long* p = (const long long*)ei;
        int half = E / 2;                     // safe int64-element range
        int nchk = half < 64 ? (half > 0 ? half : 1) : 64;
        int stride = half / nchk;
        if (stride < 1) stride = 1;
        int is64 = 1;
        for (int k = 0; k < nchk; k++) {
            long long v = p[(long long)k * stride];
            if (v < 0 || v >= (long long)N) { is64 = 0; break; }
        }
        g_is64 = is64;
    }
}

// Load 2 consecutive edge indices with one vector load (pos must be even).
__device__ __forceinline__ int2 load_idx2(const void* ei, long long pos, int is64) {
    if (is64) {
        longlong2 v = ((const longlong2*)ei)[pos >> 1];
        return make_int2((int)v.x, (int)v.y);
    }
    return ((const int2*)ei)[pos >> 1];
}

// Histogram in-degrees, 2 edges per thread (vector index load, 2 independent
// atomic chains in flight). The atomic's return value is this edge's arrival
// rank within its destination bucket — persist (dst, rank) as one STG.64
// so the fill pass needs NO atomics and never re-reads the (possibly int64)
// dst row. E=640000 is even; a scalar guard handles odd E anyway.
__global__ void k_hist(const void* ei, int E) {
    int t = blockIdx.x * blockDim.x + threadIdx.x;
    int e = t * 2;
    if (e >= E) return;
    int is64 = g_is64;
    if (e + 2 <= E) {
        int2 d = load_idx2(ei, (long long)E + e, is64);
        int r0 = atomicAdd(&g_deg[d.x], 1);
        int r1 = atomicAdd(&g_deg[d.y], 1);
        g_dr[e]     = make_int2(d.x, r0);
        g_dr[e + 1] = make_int2(d.y, r1);
    } else {
        int dst = is64 ? (int)((const long long*)ei)[(long long)E + e]
                       : ((const int*)ei)[(long long)E + e];
        int r = atomicAdd(&g_deg[dst], 1);
        g_dr[e] = make_int2(dst, r);
    }
}

// Single-block shfl-based exclusive scan: deg -> row_ptr, inv_deg.
// 4 block barriers per 1024-chunk.
__global__ void k_scan(int N) {
    __shared__ int warp_sums[32];
    __shared__ int carry_s;
    int tid = threadIdx.x;
    int w = tid >> 5;
    int lane = tid & 31;
    if (tid == 0) carry_s = 0;
    __syncthreads();

    for (int base = 0; base < N; base += 1024) {
        int i = base + tid;
        int v = (i < N) ? g_deg[i] : 0;

        // inclusive warp scan
        int s = v;
        #pragma unroll
        for (int off = 1; off < 32; off <<= 1) {
            int t = __shfl_up_sync(0xFFFFFFFFu, s, off);
            if (lane >= off) s += t;
        }
        if (lane == 31) warp_sums[w] = s;
        __syncthreads();

        // warp 0 scans the 32 warp sums (inclusive)
        if (w == 0) {
            int ws = warp_sums[lane];
            #pragma unroll
            for (int off = 1; off < 32; off <<= 1) {
                int t = __shfl_up_sync(0xFFFFFFFFu, ws, off);
                if (lane >= off) ws += t;
            }
            warp_sums[lane] = ws;
        }
        __syncthreads();

        int warp_off = (w > 0) ? warp_sums[w - 1] : 0;
        int carry = carry_s;
        if (i < N) {
            int excl = carry + warp_off + s - v;
            g_row_ptr[i] = excl;
            g_inv_deg[i] = (v > 0) ? (1.0f / (float)v) : 0.0f;
        }
        __syncthreads();                    // everyone has read carry_s
        if (tid == 0) carry_s = carry + warp_sums[31];
        __syncthreads();
    }
    if (tid == 0) g_row_ptr[N] = carry_s;
}

// Atomic-free fill, 2 edges per thread: pos = row_ptr[dst] + rank. Within
// each destination the ranks are a bijection onto [0, deg), so g_col holds
// exactly the source multiset per node — sum aggregation is order-invariant,
// so the final output is deterministic even though rank assignment isn't.
// Stores src*32 (float4-unit row offset) so the hop loop needs no multiply.
__global__ void k_fill(const void* ei, int E) {
    int t = blockIdx.x * blockDim.x + threadIdx.x;
    int e = t * 2;
    if (e >= E) return;
    int is64 = g_is64;
    if (e + 2 <= E) {
        int2 s = load_idx2(ei, e, is64);
        int2 dr0 = g_dr[e];
        int2 dr1 = g_dr[e + 1];
        g_col[g_row_ptr[dr0.x] + dr0.y] = s.x * 32;
        g_col[g_row_ptr[dr1.x] + dr1.y] = s.y * 32;
    } else {
        int src = is64 ? (int)((const long long*)ei)[e] : ((const int*)ei)[e];
        int2 dr = g_dr[e];
        g_col[g_row_ptr[dr.x] + dr.y] = src * 32;
    }
}

// ---------------- hop: one WARP per node ----------------
// Lane l owns channels [4l, 4l+3] as one float4 -> the warp covers the full
// 512B row (4 contiguous 128B L2 lines). Walk the node's CSR list with 8
// independent LDG.128 in flight (MLP_eff=8 keeps exposed L2 latency under
// the per-warp BW share), then a 4-wide tail step so the worst-case tail
// exposes <=3 serial L2 latencies instead of 7. No smem, no __syncthreads.
//
// DO_GATE: on the last hop the warp already holds the h3 row in registers, so
// the softmax gate (x,h1,h2,h3 blend) is fused into the epilogue — saves the
// 5.1 MB h3 store, its re-read, and a kernel launch.
template <bool DO_GATE>
__global__ void __launch_bounds__(256) k_hop(const float* __restrict__ x,
                                             int step, int N,
                                             const float* __restrict__ gw,
                                             const float* __restrict__ gb,
                                             float* __restrict__ out) {
    int gwid = (blockIdx.x * blockDim.x + threadIdx.x) >> 5;
    if (gwid >= N) return;
    int lane = threadIdx.x & 31;

    const float4* __restrict__ hprev =
        (const float4*)((step == 0) ? x : g_h[step - 1]);

    int beg = g_row_ptr[gwid];
    int end = g_row_ptr[gwid + 1];

    // Hoisted for the gate epilogue: issue the gate-weight load early so it
    // overlaps the gather loop instead of extending the epilogue.
    float4 g;
    float bias = 0.0f;
    if (DO_GATE) {
        g = __ldg(&((const float4*)gw)[lane]);
        bias = gb[0];
    }

    float4 acc = make_float4(0.f, 0.f, 0.f, 0.f);

    int e = beg;
    for (; e + 8 <= end; e += 8) {
        // 8 col offsets first (contiguous, uniform across the warp), then 8
        // independent LDG.128 feature loads in flight before any consumer.
        int c0 = g_col[e];     int c1 = g_col[e + 1];
        int c2 = g_col[e + 2]; int c3 = g_col[e + 3];
        int c4 = g_col[e + 4]; int c5 = g_col[e + 5];
        int c6 = g_col[e + 6]; int c7 = g_col[e + 7];
        float4 a0 = __ldg(&hprev[(size_t)(c0 + lane)]);
        float4 a1 = __ldg(&hprev[(size_t)(c1 + lane)]);
        float4 a2 = __ldg(&hprev[(size_t)(c2 + lane)]);
        float4 a3 = __ldg(&hprev[(size_t)(c3 + lane)]);
        float4 a4 = __ldg(&hprev[(size_t)(c4 + lane)]);
        float4 a5 = __ldg(&hprev[(size_t)(c5 + lane)]);
        float4 a6 = __ldg(&hprev[(size_t)(c6 + lane)]);
        float4 a7 = __ldg(&hprev[(size_t)(c7 + lane)]);
        acc.x += ((a0.x + a1.x) + (a2.x + a3.x)) + ((a4.x + a5.x) + (a6.x + a7.x));
        acc.y += ((a0.y + a1.y) + (a2.y + a3.y)) + ((a4.y + a5.y) + (a6.y + a7.y));
        acc.z += ((a0.z + a1.z) + (a2.z + a3.z)) + ((a4.z + a5.z) + (a6.z + a7.z));
        acc.w += ((a0.w + a1.w) + (a2.w + a3.w)) + ((a4.w + a5.w) + (a6.w + a7.w));
    }
    if (e + 4 <= end) {
        int c0 = g_col[e];     int c1 = g_col[e + 1];
        int c2 = g_col[e + 2]; int c3 = g_col[e + 3];
        float4 a0 = __ldg(&hprev[(size_t)(c0 + lane)]);
        float4 a1 = __ldg(&hprev[(size_t)(c1 + lane)]);
        float4 a2 = __ldg(&hprev[(size_t)(c2 + lane)]);
        float4 a3 = __ldg(&hprev[(size_t)(c3 + lane)]);
        acc.x += (a0.x + a1.x) + (a2.x + a3.x);
        acc.y += (a0.y + a1.y) + (a2.y + a3.y);
        acc.z += (a0.z + a1.z) + (a2.z + a3.z);
        acc.w += (a0.w + a1.w) + (a2.w + a3.w);
        e += 4;
    }
    for (; e < end; e++) {
        float4 a = __ldg(&hprev[(size_t)(g_col[e] + lane)]);
        acc.x += a.x; acc.y += a.y; acc.z += a.z; acc.w += a.w;
    }

    float id = g_inv_deg[gwid];
    acc.x *= id; acc.y *= id; acc.z *= id; acc.w *= id;

    if (!DO_GATE) {
        ((float4*)g_h[step])[(size_t)gwid * 32 + lane] = acc;
        return;
    }

    // ---- fused gate epilogue (acc == h3 row chunk for this lane) ----
    const float4* h0 = (const float4*)x      + (size_t)gwid * 32;
    const float4* h1 = (const float4*)g_h[0] + (size_t)gwid * 32;
    const float4* h2 = (const float4*)g_h[1] + (size_t)gwid * 32;

    float4 a = __ldg(&h0[lane]);
    float4 b = __ldg(&h1[lane]);
    float4 c = __ldg(&h2[lane]);

    float s0 = a.x * g.x + a.y * g.y + a.z * g.z + a.w * g.w;
    float s1 = b.x * g.x + b.y * g.y + b.z * g.z + b.w * g.w;
    float s2 = c.x * g.x + c.y * g.y + c.z * g.z + c.w * g.w;
    float s3 = acc.x * g.x + acc.y * g.y + acc.z * g.z + acc.w * g.w;
    #pragma unroll
    for (int off = 16; off; off >>= 1) {
        s0 += __shfl_xor_sync(0xFFFFFFFFu, s0, off);
        s1 += __shfl_xor_sync(0xFFFFFFFFu, s1, off);
        s2 += __shfl_xor_sync(0xFFFFFFFFu, s2, off);
        s3 += __shfl_xor_sync(0xFFFFFFFFu, s3, off);
    }
    s0 += bias; s1 += bias; s2 += bias; s3 += bias;

    float m = fmaxf(fmaxf(s0, s1), fmaxf(s2, s3));
    float e0 = __expf(s0 - m), e1 = __expf(s1 - m);
    float e2 = __expf(s2 - m), e3 = __expf(s3 - m);
    float inv = 1.0f / (e0 + e1 + e2 + e3);
    float w0 = e0 * inv, w1 = e1 * inv, w2 = e2 * inv, w3 = e3 * inv;

    float4 o;
    o.x = w0 * a.x + w1 * b.x + w2 * c.x + w3 * acc.x;
    o.y = w0 * a.y + w1 * b.y + w2 * c.y + w3 * acc.y;
    o.z = w0 * a.z + w1 * b.z + w2 * c.z + w3 * acc.z;
    o.w = w0 * a.w + w1 * b.w + w2 * c.w + w3 * acc.w;
    ((float4*)out)[(size_t)gwid * 32 + lane] = o;
}

extern "C" void kernel_launch(void* const* d_in, const int* in_sizes, int n_in,
                              void* d_out, int out_size) {
    const float* x  = (const float*)d_in[0];
    const void*  ei = d_in[1];
    const float* gw = (const float*)d_in[2];
    const float* gb = (const float*)d_in[3];
    float* out = (float*)d_out;

    int N = in_sizes[0] / C;
    int E = in_sizes[1] / 2;
    if (N > MAXN) N = MAXN;
    if (E > MAXE) E = MAXE;

    int warp_blocks = (N * 32 + 255) / 256;
    int pair_blocks = ((E + 1) / 2 + 255) / 256;

    k_init<<<(N + 255) / 256, 256>>>(ei, E, N);
    k_hist<<<pair_blocks, 256>>>(ei, E);
    k_scan<<<1, 1024>>>(N);
    k_fill<<<pair_blocks, 256>>>(ei, E);
    k_hop<false><<<warp_blocks, 256>>>(x, 0, N, gw, gb, out);
    k_hop<false><<<warp_blocks, 256>>>(x, 1, N, gw, gb, out);
    k_hop<true ><<<warp_blocks, 256>>>(x, 2, N, gw, gb, out);
}